// round 5
// baseline (speedup 1.0000x reference)
#include <cuda_runtime.h>
#include <cstdint>

// FreqActivation (real-part output):
//   F(a,p) = relu(a) * cos(pi * tanh(p))
//   out(b,h,w,c) = F(in(b,h,w,c))            if h==0 || w==0 || h+w<=256  (direct D)
//                = F(in(b,256-h,256-w,c))    otherwise (conj keeps Re)
// Direct threads write themselves; D cells with h,w>=1 && h+w<=255 also write the
// unique mirror cell. 8 channels per thread: 2x independent 32B evict_last loads
// (MLP=2), cos(pi*t) as an FFMA Horner polynomial in t=tanh(p) (no MUFU cos).

#define HW 256
#define NCELLS (8 * 256 * 256)   // B*H*W = 524288

// tanh(x) = 1 - 2/(exp(2x)+1)   (ex2.approx + rcp.approx; abs err ~1e-6)
__device__ __forceinline__ float fast_tanh(float x) {
    const float LOG2E_2 = 2.88539008177792681472f;  // 2*log2(e)
    float e; asm("ex2.approx.f32 %0, %1;" : "=f"(e) : "f"(x * LOG2E_2));
    float r; asm("rcp.approx.f32 %0, %1;" : "=f"(r) : "f"(e + 1.0f));
    return fmaf(-2.0f, r, 1.0f);
}

// cos(pi*t) for t in [-1,1]: even Taylor, 7 terms, |err| <= 4.3e-6.
__device__ __forceinline__ float cospi_poly(float t) {
    float y = t * t;
    float p = -1.0463756e-4f;                 // -pi^14/14!
    p = fmaf(p, y,  1.9295743e-3f);           //  pi^12/12!
    p = fmaf(p, y, -2.5806891390e-2f);        // -pi^10/10!
    p = fmaf(p, y,  2.35330630359e-1f);       //  pi^8/8!
    p = fmaf(p, y, -1.33526276885f);          // -pi^6/6!
    p = fmaf(p, y,  4.05871212642f);          //  pi^4/4!
    p = fmaf(p, y, -4.93480220054f);          // -pi^2/2!
    return fmaf(p, y, 1.0f);
}

__device__ __forceinline__ float chan(float amp, float ph) {
    return fmaxf(amp, 0.0f) * cospi_poly(fast_tanh(ph));
}

// 32-byte load with L2 evict_last (.v4.b64 shape required on sm_103).
__device__ __forceinline__ void ld32_keep(const void* p, float f[8]) {
    uint64_t d0, d1, d2, d3;
    asm volatile("ld.global.nc.L2::evict_last.v4.b64 {%0,%1,%2,%3}, [%4];"
                 : "=l"(d0), "=l"(d1), "=l"(d2), "=l"(d3) : "l"(p));
    f[0] = __uint_as_float((unsigned)d0); f[1] = __uint_as_float((unsigned)(d0 >> 32));
    f[2] = __uint_as_float((unsigned)d1); f[3] = __uint_as_float((unsigned)(d1 >> 32));
    f[4] = __uint_as_float((unsigned)d2); f[5] = __uint_as_float((unsigned)(d2 >> 32));
    f[6] = __uint_as_float((unsigned)d3); f[7] = __uint_as_float((unsigned)(d3 >> 32));
}
__device__ __forceinline__ void st_stream(float4* p, float x, float y, float z, float w) {
    asm volatile("st.global.cs.v4.f32 [%0], {%1,%2,%3,%4};"
                 :: "l"(p), "f"(x), "f"(y), "f"(z), "f"(w) : "memory");
}

// ---------------- real-only output path (out_size = 16,777,216 float32) -------------
// Per thread: 8 channels = 64B input (2x32B loads), 32B direct out, 32B mirror out.
__global__ __launch_bounds__(256)
void freq_act_real_kernel(const float4* __restrict__ in, float4* __restrict__ out,
                          unsigned in_cap4, unsigned out_cap4) {
    unsigned tid  = blockIdx.x * blockDim.x + threadIdx.x;  // 0 .. NCELLS*4-1
    unsigned cell = tid >> 2;
    unsigned q    = tid & 3u;                                // 8-channel chunk
    unsigned w    = cell & 255u;
    unsigned h    = (cell >> 8) & 255u;
    unsigned hw   = h + w;

    bool direct = (h == 0u) || (w == 0u) || (hw <= 256u);
    if (!direct) return;

    unsigned ii = cell * 16u + 4u * q;        // float4 index, 32B-pair aligned
    if (ii + 3u >= in_cap4) return;
    float f[16];                              // (amp,ph) x 8 channels
    ld32_keep(&in[ii],      f);
    ld32_keep(&in[ii + 2u], f + 8);

    float o[8];
#pragma unroll
    for (int j = 0; j < 8; j++)
        o[j] = chan(f[2 * j], f[2 * j + 1]);

    unsigned oi = cell * 8u + 2u * q;
    if (oi + 1u < out_cap4) {
        st_stream(&out[oi],      o[0], o[1], o[2], o[3]);
        st_stream(&out[oi + 1u], o[4], o[5], o[6], o[7]);
    }

    if (h >= 1u && w >= 1u && hw <= 255u) {   // unique mirror source
        unsigned mcell = (cell & ~0xFFFFu) | ((HW - h) << 8) | (HW - w);
        unsigned mo = mcell * 8u + 2u * q;
        if (mo + 1u < out_cap4) {             // conj keeps the real part
            st_stream(&out[mo],      o[0], o[1], o[2], o[3]);
            st_stream(&out[mo + 1u], o[4], o[5], o[6], o[7]);
        }
    }
}

// ---------------- interleaved complex fallback (unused when out is float32) ---------
__device__ __forceinline__ float fast_sin(float x) {
    float r; asm("sin.approx.f32 %0, %1;" : "=f"(r) : "f"(x)); return r;
}
__device__ __forceinline__ float fast_cos(float x) {
    float r; asm("cos.approx.f32 %0, %1;" : "=f"(r) : "f"(x)); return r;
}

__global__ __launch_bounds__(256)
void freq_act_cplx_kernel(const float4* __restrict__ in, float4* __restrict__ out,
                          unsigned in_cap4, unsigned out_cap4) {
    unsigned tid  = blockIdx.x * blockDim.x + threadIdx.x;
    unsigned cell = tid >> 4;
    unsigned q    = tid & 15u;
    unsigned w    = cell & 255u;
    unsigned h    = (cell >> 8) & 255u;
    unsigned hw   = h + w;

    bool direct = (h == 0u) || (w == 0u) || (hw <= 256u);
    if (!direct) return;

    unsigned ii = cell * 16u + q;
    if (ii >= in_cap4) return;
    float4 v = __ldg(&in[ii]);

    const float PI_F = 3.14159265358979323846f;
    float amp0 = fmaxf(v.x, 0.0f), ph0 = PI_F * fast_tanh(v.y);
    float amp1 = fmaxf(v.z, 0.0f), ph1 = PI_F * fast_tanh(v.w);

    float4 o;
    o.x = amp0 * fast_cos(ph0);  o.y = amp0 * fast_sin(ph0);
    o.z = amp1 * fast_cos(ph1);  o.w = amp1 * fast_sin(ph1);

    unsigned oi = cell * 16u + q;
    if (oi < out_cap4) out[oi] = o;

    if (h >= 1u && w >= 1u && hw <= 255u) {
        unsigned mcell = (cell & ~0xFFFFu) | ((HW - h) << 8) | (HW - w);
        unsigned mo = mcell * 16u + q;
        float4 m; m.x = o.x; m.y = -o.y; m.z = o.z; m.w = -o.w;
        if (mo < out_cap4) out[mo] = m;
    }
}

extern "C" void kernel_launch(void* const* d_in, const int* in_sizes, int n_in,
                              void* d_out, int out_size) {
    (void)n_in;
    const float4* in  = (const float4*)d_in[0];
    float4*       out = (float4*)d_out;
    unsigned in_cap4 = (unsigned)(in_sizes[0] / 4);

    if (out_size <= 16777216) {
        unsigned out_cap4 = (unsigned)(out_size / 4);
        const int total = NCELLS * 4;          // 2,097,152 threads
        freq_act_real_kernel<<<total / 256, 256>>>(in, out, in_cap4, out_cap4);
    } else {
        long long floats = (out_size >= 134217728) ? (long long)out_size / 4
                                                   : (long long)out_size;
        unsigned out_cap4 = (unsigned)(floats / 4);
        const int total = NCELLS * 16;
        freq_act_cplx_kernel<<<total / 256, 256>>>(in, out, in_cap4, out_cap4);
    }
}

// round 7
// speedup vs baseline: 1.0861x; 1.0861x over previous
#include <cuda_runtime.h>
#include <cstdint>

// FreqActivation (real-part output):
//   F(a,p) = relu(a) * cos(pi * tanh(p))
//   out(b,h,w,c) = F(in(b,h,w,c))           if h==0 || w==0 || h+w<=256  (direct D)
//                = F(in(b,256-h,256-w,c))   otherwise (conj keeps Re)
// Compact grid: threads launched ONLY for direct cells (33151 per b-slice of
// 65536). tid -> (h,w) via closed-form inverse triangular index. 8 threads per
// cell, 4 channels each (one 32B load, one 16B store, + mirror store when the
// cell is a mirror source: h,w>=1 && h+w<=255).

#define HW 256
#define N1 33151u                 // live cells per b-slice
#define NLIVE (8u * N1)           // 265208 live cells
#define TOTTHREADS (NLIVE * 8u)   // 2,121,664 threads (8 per cell = 32 channels)

// tanh(x) = 1 - 2/(exp(2x)+1)   (ex2.approx + rcp.approx; abs err ~1e-6)
__device__ __forceinline__ float fast_tanh(float x) {
    const float LOG2E_2 = 2.88539008177792681472f;  // 2*log2(e)
    float e; asm("ex2.approx.f32 %0, %1;" : "=f"(e) : "f"(x * LOG2E_2));
    float r; asm("rcp.approx.f32 %0, %1;" : "=f"(r) : "f"(e + 1.0f));
    return fmaf(-2.0f, r, 1.0f);
}
// cos(pi*t) for t in [-1,1]: even Taylor, 7 terms, |err| <= 4.3e-6.
__device__ __forceinline__ float cospi_poly(float t) {
    float y = t * t;
    float p = -1.0463756e-4f;
    p = fmaf(p, y,  1.9295743e-3f);
    p = fmaf(p, y, -2.5806891390e-2f);
    p = fmaf(p, y,  2.35330630359e-1f);
    p = fmaf(p, y, -1.33526276885f);
    p = fmaf(p, y,  4.05871212642f);
    p = fmaf(p, y, -4.93480220054f);
    return fmaf(p, y, 1.0f);
}
__device__ __forceinline__ float chan(float amp, float ph) {
    return fmaxf(amp, 0.0f) * cospi_poly(fast_tanh(ph));
}

// 32-byte load with L2 evict_last (.v4.b64 shape required on sm_103).
__device__ __forceinline__ void ld32_keep(const void* p, float f[8]) {
    uint64_t d0, d1, d2, d3;
    asm volatile("ld.global.nc.L2::evict_last.v4.b64 {%0,%1,%2,%3}, [%4];"
                 : "=l"(d0), "=l"(d1), "=l"(d2), "=l"(d3) : "l"(p));
    f[0] = __uint_as_float((unsigned)d0); f[1] = __uint_as_float((unsigned)(d0 >> 32));
    f[2] = __uint_as_float((unsigned)d1); f[3] = __uint_as_float((unsigned)(d1 >> 32));
    f[4] = __uint_as_float((unsigned)d2); f[5] = __uint_as_float((unsigned)(d2 >> 32));
    f[6] = __uint_as_float((unsigned)d3); f[7] = __uint_as_float((unsigned)(d3 >> 32));
}
__device__ __forceinline__ void st_stream(float4* p, float x, float y, float z, float w) {
    asm volatile("st.global.cs.v4.f32 [%0], {%1,%2,%3,%4};"
                 :: "l"(p), "f"(x), "f"(y), "f"(z), "f"(w) : "memory");
}

// trow_off(u) = u*(513-u)/2 = live cells in rows h=1..u
__device__ __forceinline__ unsigned trow_off(unsigned u) {
    return (u * (513u - u)) >> 1;
}

// ---------------- real-only output path (out_size = 16,777,216 float32) -------------
__global__ __launch_bounds__(256)
void freq_act_real_kernel(const float4* __restrict__ in, float4* __restrict__ out,
                          unsigned in_cap4, unsigned out_cap4) {
    unsigned tid = blockIdx.x * blockDim.x + threadIdx.x;
    if (tid >= TOTTHREADS) return;
    unsigned s = tid >> 3;          // live-cell index across all b
    unsigned q = tid & 7u;          // 4-channel chunk within cell (0..7)
    unsigned b = s / N1;            // const-div -> mul.hi
    unsigned r = s - b * N1;        // live-cell index within slice

    unsigned h, w;
    if (r < 256u) {                 // row h=0: fully live
        h = 0u; w = r;
    } else {
        unsigned rp = r - 256u;     // 0 .. 32894, rows h=1..255, width 257-h
        // u = max{u : trow_off(u) <= rp}, h = u+1
        float disc = (float)(263169u - 8u * rp);     // 513^2 - 8*rp (exact in fp32)
        unsigned u = (unsigned)((513.0f - __fsqrt_rn(disc)) * 0.5f);
        if (u > 254u) u = 254u;
        while (u > 0u && trow_off(u) > rp) --u;      // sqrt-rounding fix-up
        while (trow_off(u + 1u) <= rp) ++u;
        h = u + 1u;
        w = rp - trow_off(u);       // 0 .. 256-h
    }
    unsigned hw = h + w;
    unsigned cell = (b << 16) | (h << 8) | w;

    unsigned ii = cell * 16u + 2u * q;        // float4 index (32B-aligned pair)
    if (ii + 1u >= in_cap4) return;
    float f[8];                                // amp0 ph0 amp1 ph1 amp2 ph2 amp3 ph3
    ld32_keep(&in[ii], f);

    float o0 = chan(f[0], f[1]);
    float o1 = chan(f[2], f[3]);
    float o2 = chan(f[4], f[5]);
    float o3 = chan(f[6], f[7]);

    unsigned oi = cell * 8u + q;
    if (oi < out_cap4) st_stream(&out[oi], o0, o1, o2, o3);

    if (h >= 1u && w >= 1u && hw <= 255u) {    // unique mirror source
        unsigned mcell = (b << 16) | ((HW - h) << 8) | (HW - w);
        unsigned mo = mcell * 8u + q;
        if (mo < out_cap4) st_stream(&out[mo], o0, o1, o2, o3);  // conj keeps Re
    }
}

// ---------------- interleaved complex fallback (unused when out is float32) ---------
__device__ __forceinline__ float fast_sin(float x) {
    float r; asm("sin.approx.f32 %0, %1;" : "=f"(r) : "f"(x)); return r;
}
__device__ __forceinline__ float fast_cos(float x) {
    float r; asm("cos.approx.f32 %0, %1;" : "=f"(r) : "f"(x)); return r;
}
__global__ __launch_bounds__(256)
void freq_act_cplx_kernel(const float4* __restrict__ in, float4* __restrict__ out,
                          unsigned in_cap4, unsigned out_cap4) {
    unsigned tid  = blockIdx.x * blockDim.x + threadIdx.x;
    unsigned cell = tid >> 4;
    unsigned q    = tid & 15u;
    unsigned w    = cell & 255u;
    unsigned h    = (cell >> 8) & 255u;
    unsigned hw   = h + w;
    bool direct = (h == 0u) || (w == 0u) || (hw <= 256u);
    if (!direct) return;
    unsigned ii = cell * 16u + q;
    if (ii >= in_cap4) return;
    float4 v = __ldg(&in[ii]);
    const float PI_F = 3.14159265358979323846f;
    float amp0 = fmaxf(v.x, 0.0f), ph0 = PI_F * fast_tanh(v.y);
    float amp1 = fmaxf(v.z, 0.0f), ph1 = PI_F * fast_tanh(v.w);
    float4 o;
    o.x = amp0 * fast_cos(ph0);  o.y = amp0 * fast_sin(ph0);
    o.z = amp1 * fast_cos(ph1);  o.w = amp1 * fast_sin(ph1);
    unsigned oi = cell * 16u + q;
    if (oi < out_cap4) out[oi] = o;
    if (h >= 1u && w >= 1u && hw <= 255u) {
        unsigned mcell = (cell & ~0xFFFFu) | ((HW - h) << 8) | (HW - w);
        unsigned mo = mcell * 16u + q;
        float4 m; m.x = o.x; m.y = -o.y; m.z = o.z; m.w = -o.w;
        if (mo < out_cap4) out[mo] = m;
    }
}

extern "C" void kernel_launch(void* const* d_in, const int* in_sizes, int n_in,
                              void* d_out, int out_size) {
    (void)n_in;
    const float4* in  = (const float4*)d_in[0];
    float4*       out = (float4*)d_out;
    unsigned in_cap4 = (unsigned)(in_sizes[0] / 4);

    if (out_size <= 16777216) {
        unsigned out_cap4 = (unsigned)(out_size / 4);
        const unsigned grid = (TOTTHREADS + 255u) / 256u;   // 8288 blocks
        freq_act_real_kernel<<<grid, 256>>>(in, out, in_cap4, out_cap4);
    } else {
        long long floats = (out_size >= 134217728) ? (long long)out_size / 4
                                                   : (long long)out_size;
        unsigned out_cap4 = (unsigned)(floats / 4);
        const unsigned total = 524288u * 16u;
        freq_act_cplx_kernel<<<total / 256u, 256>>>(in, out, in_cap4, out_cap4);
    }
}

// round 8
// speedup vs baseline: 1.0977x; 1.0107x over previous
#include <cuda_runtime.h>
#include <cstdint>

// FreqActivation (real-part output):
//   F(a,p) = relu(a) * cos(pi * tanh(p))
//   out(b,h,w,c) = F(in(b,h,w,c))           if h==0 || w==0 || h+w<=256  (direct D)
//                = F(in(b,256-h,256-w,c))   otherwise (conj keeps Re)
// Compact grid over direct cells only (33151 per b-slice), 8 threads/cell.
// tid -> (h,w) via row-pairing map: rows h and 255-v (h=v+2) have widths
// (255-v) and (v+2) summing to 257, so r-512 decomposes as v*257+k with one
// constant divide. Rows 0 and 1 are width 256 and handled by r<512.

#define HW 256
#define N1 33151u                 // live cells per b-slice
#define NLIVE (8u * N1)           // 265208 live cells
#define TOTTHREADS (NLIVE * 8u)   // 2,121,664 threads (8 per cell = 32 channels)

// tanh via ex2+rcp (abs err ~1e-6), then cos via MUFU (arg in [-pi,pi]).
__device__ __forceinline__ float fast_cos(float x) {
    float r; asm("cos.approx.f32 %0, %1;" : "=f"(r) : "f"(x)); return r;
}
__device__ __forceinline__ float fast_tanh(float x) {
    const float LOG2E_2 = 2.88539008177792681472f;  // 2*log2(e)
    float e; asm("ex2.approx.f32 %0, %1;" : "=f"(e) : "f"(x * LOG2E_2));
    float r; asm("rcp.approx.f32 %0, %1;" : "=f"(r) : "f"(e + 1.0f));
    return fmaf(-2.0f, r, 1.0f);
}
__device__ __forceinline__ float chan(float amp, float ph) {
    const float PI_F = 3.14159265358979323846f;
    return fmaxf(amp, 0.0f) * fast_cos(PI_F * fast_tanh(ph));
}

// 32-byte load with L2 evict_last (.v4.b64 shape required on sm_103).
__device__ __forceinline__ void ld32_keep(const void* p, float f[8]) {
    uint64_t d0, d1, d2, d3;
    asm volatile("ld.global.nc.L2::evict_last.v4.b64 {%0,%1,%2,%3}, [%4];"
                 : "=l"(d0), "=l"(d1), "=l"(d2), "=l"(d3) : "l"(p));
    f[0] = __uint_as_float((unsigned)d0); f[1] = __uint_as_float((unsigned)(d0 >> 32));
    f[2] = __uint_as_float((unsigned)d1); f[3] = __uint_as_float((unsigned)(d1 >> 32));
    f[4] = __uint_as_float((unsigned)d2); f[5] = __uint_as_float((unsigned)(d2 >> 32));
    f[6] = __uint_as_float((unsigned)d3); f[7] = __uint_as_float((unsigned)(d3 >> 32));
}
__device__ __forceinline__ void st_stream(float4* p, float x, float y, float z, float w) {
    asm volatile("st.global.cs.v4.f32 [%0], {%1,%2,%3,%4};"
                 :: "l"(p), "f"(x), "f"(y), "f"(z), "f"(w) : "memory");
}

// ---------------- real-only output path (out_size = 16,777,216 float32) -------------
__global__ __launch_bounds__(256)
void freq_act_real_kernel(const float4* __restrict__ in, float4* __restrict__ out,
                          unsigned in_cap4, unsigned out_cap4) {
    unsigned tid = blockIdx.x * blockDim.x + threadIdx.x;
    if (tid >= TOTTHREADS) return;
    unsigned s = tid >> 3;          // live-cell index across all b
    unsigned q = tid & 7u;          // 4-channel chunk within cell (0..7)
    unsigned b = s / N1;            // const-div -> mul.hi
    unsigned r = s - b * N1;        // live-cell index within slice

    unsigned h, w;
    if (r < 512u) {                 // rows 0 and 1, each width 256
        h = r >> 8;  w = r & 255u;
    } else {
        unsigned r2 = r - 512u;     // rows 2..255 as 127 pairs of combined width 257
        unsigned v  = r2 / 257u;    // const-div -> mul.hi  (v = 0..126)
        unsigned k  = r2 - v * 257u;
        unsigned wa = 254u - v;     // row (v+2) has w in 0..254-v (width 255-v)
        bool first = (k <= wa);
        h = first ? (v + 2u)   : (255u - v);
        w = first ? k          : (k - (255u - v));   // second row width v+2
    }
    unsigned hw = h + w;
    unsigned cell = (b << 16) | (h << 8) | w;

    unsigned ii = cell * 16u + 2u * q;        // float4 index (32B-aligned pair)
    if (ii + 1u >= in_cap4) return;
    float f[8];                                // amp0 ph0 ... amp3 ph3
    ld32_keep(&in[ii], f);

    float o0 = chan(f[0], f[1]);
    float o1 = chan(f[2], f[3]);
    float o2 = chan(f[4], f[5]);
    float o3 = chan(f[6], f[7]);

    unsigned oi = cell * 8u + q;
    if (oi < out_cap4) st_stream(&out[oi], o0, o1, o2, o3);

    if (h >= 1u && w >= 1u && hw <= 255u) {    // unique mirror source
        unsigned mcell = (b << 16) | ((HW - h) << 8) | (HW - w);
        unsigned mo = mcell * 8u + q;
        if (mo < out_cap4) st_stream(&out[mo], o0, o1, o2, o3);  // conj keeps Re
    }
}

// ---------------- interleaved complex fallback (unused when out is float32) ---------
__device__ __forceinline__ float fast_sin(float x) {
    float r; asm("sin.approx.f32 %0, %1;" : "=f"(r) : "f"(x)); return r;
}
__global__ __launch_bounds__(256)
void freq_act_cplx_kernel(const float4* __restrict__ in, float4* __restrict__ out,
                          unsigned in_cap4, unsigned out_cap4) {
    unsigned tid  = blockIdx.x * blockDim.x + threadIdx.x;
    unsigned cell = tid >> 4;
    unsigned q    = tid & 15u;
    unsigned w    = cell & 255u;
    unsigned h    = (cell >> 8) & 255u;
    unsigned hw   = h + w;
    bool direct = (h == 0u) || (w == 0u) || (hw <= 256u);
    if (!direct) return;
    unsigned ii = cell * 16u + q;
    if (ii >= in_cap4) return;
    float4 v = __ldg(&in[ii]);
    const float PI_F = 3.14159265358979323846f;
    float amp0 = fmaxf(v.x, 0.0f), ph0 = PI_F * fast_tanh(v.y);
    float amp1 = fmaxf(v.z, 0.0f), ph1 = PI_F * fast_tanh(v.w);
    float4 o;
    o.x = amp0 * fast_cos(ph0);  o.y = amp0 * fast_sin(ph0);
    o.z = amp1 * fast_cos(ph1);  o.w = amp1 * fast_sin(ph1);
    unsigned oi = cell * 16u + q;
    if (oi < out_cap4) out[oi] = o;
    if (h >= 1u && w >= 1u && hw <= 255u) {
        unsigned mcell = (cell & ~0xFFFFu) | ((HW - h) << 8) | (HW - w);
        unsigned mo = mcell * 16u + q;
        float4 m; m.x = o.x; m.y = -o.y; m.z = o.z; m.w = -o.w;
        if (mo < out_cap4) out[mo] = m;
    }
}

extern "C" void kernel_launch(void* const* d_in, const int* in_sizes, int n_in,
                              void* d_out, int out_size) {
    (void)n_in;
    const float4* in  = (const float4*)d_in[0];
    float4*       out = (float4*)d_out;
    unsigned in_cap4 = (unsigned)(in_sizes[0] / 4);

    if (out_size <= 16777216) {
        unsigned out_cap4 = (unsigned)(out_size / 4);
        const unsigned grid = (TOTTHREADS + 255u) / 256u;   // 8288 blocks
        freq_act_real_kernel<<<grid, 256>>>(in, out, in_cap4, out_cap4);
    } else {
        long long floats = (out_size >= 134217728) ? (long long)out_size / 4
                                                   : (long long)out_size;
        unsigned out_cap4 = (unsigned)(floats / 4);
        const unsigned total = 524288u * 16u;
        freq_act_cplx_kernel<<<total / 256u, 256>>>(in, out, in_cap4, out_cap4);
    }
}